// round 3
// baseline (speedup 1.0000x reference)
#include <cuda_runtime.h>
#include <cstdint>

// PARAFAC / CP reconstruction: out[a,b,c] = sum_k f0[k,a] * f1[k,b] * f2[k,c]
// A = B = C = 512, RANK = 16, fp32. 536 MB output -> store/FMA co-bound.
//
// Round-3: f32x2 lanes paired along K (not C):
//   acc[c] (f32x2) accumulates (even-k sum, odd-k sum); one horizontal FADD at end.
//   - g pairs (g[2p],g[2p+1]) come PRE-PACKED from contiguous shared memory (no splat movs)
//   - f2 transposed-packed into 32 ull regs once per block: f2p[p][c] = (f2[2p,c], f2[2p+1,c])
//   - per j per thread: 4x LDS.128 + 32x FFMA2 + 4x FADD + 1x STG.128  (round 2 had +16 movs)
//   - launch_bounds(128,5): reg cap 102 -> 20 warps/SM for latency hiding

#define A_DIM 512
#define B_DIM 512
#define C_DIM 512
#define RANK  16
#define BCHUNK 64
#define NTHREADS 128   // 128 c-lanes x 4 c each = 512 c

typedef unsigned long long ull;

__device__ __forceinline__ ull pack2(float lo, float hi) {
    ull r;
    asm("mov.b64 %0, {%1,%2};" : "=l"(r) : "r"(__float_as_uint(lo)), "r"(__float_as_uint(hi)));
    return r;
}

__global__ __launch_bounds__(NTHREADS, 5)
void parafac_kernel(const float* __restrict__ f0,
                    const float* __restrict__ f1,
                    const float* __restrict__ f2,
                    float* __restrict__ out)
{
    // g k-major & contiguous: gsh[j][k] = f0[k][a]*f1[k][b0+j]
    // -> adjacent (k, k+1) floats form the packed f32x2 operand directly.
    __shared__ __align__(16) float gsh[BCHUNK][RANK];

    const int a  = blockIdx.y;
    const int b0 = blockIdx.x * BCHUNK;
    const int t  = threadIdx.x;
    const int c0 = t * 4;   // thread's fixed c-quad

    // ---- f2 transposed pack (once per block): f2p[p][c] = (f2[2p][c0+c], f2[2p+1][c0+c]) ----
    ull f2p[RANK / 2][4];
#pragma unroll
    for (int p = 0; p < RANK / 2; p++) {
        float4 e = *reinterpret_cast<const float4*>(f2 + (2 * p + 0) * C_DIM + c0);
        float4 o = *reinterpret_cast<const float4*>(f2 + (2 * p + 1) * C_DIM + c0);
        f2p[p][0] = pack2(e.x, o.x);
        f2p[p][1] = pack2(e.y, o.y);
        f2p[p][2] = pack2(e.z, o.z);
        f2p[p][3] = pack2(e.w, o.w);
    }

    // ---- precompute g: 64*16 = 1024 entries, 128 threads -> 8 each ----
#pragma unroll
    for (int i = 0; i < (BCHUNK * RANK) / NTHREADS; i++) {
        int idx = t + i * NTHREADS;
        int j = idx >> 4;     // b offset within chunk
        int k = idx & 15;     // rank index
        gsh[j][k] = f0[k * A_DIM + a] * f1[k * B_DIM + b0 + j];
    }
    __syncthreads();

    float* orow = out + (size_t)a * (B_DIM * C_DIM) + (size_t)b0 * C_DIM + c0;

#pragma unroll 2
    for (int j = 0; j < BCHUNK; j++) {
        // 4x LDS.128 (broadcast): 8 pre-packed (g_even, g_odd) pairs
        const ulonglong2* gj = reinterpret_cast<const ulonglong2*>(gsh[j]);
        ulonglong2 u0 = gj[0], u1 = gj[1], u2 = gj[2], u3 = gj[3];
        ull gp[RANK / 2] = { u0.x, u0.y, u1.x, u1.y, u2.x, u2.y, u3.x, u3.y };

        // 4 independent f32x2 accumulator chains (one per c); lanes = (even-k, odd-k) partial sums
        ull acc0 = 0ull, acc1 = 0ull, acc2 = 0ull, acc3 = 0ull;
#pragma unroll
        for (int p = 0; p < RANK / 2; p++) {
            asm("fma.rn.f32x2 %0, %1, %2, %0;" : "+l"(acc0) : "l"(f2p[p][0]), "l"(gp[p]));
            asm("fma.rn.f32x2 %0, %1, %2, %0;" : "+l"(acc1) : "l"(f2p[p][1]), "l"(gp[p]));
            asm("fma.rn.f32x2 %0, %1, %2, %0;" : "+l"(acc2) : "l"(f2p[p][2]), "l"(gp[p]));
            asm("fma.rn.f32x2 %0, %1, %2, %0;" : "+l"(acc3) : "l"(f2p[p][3]), "l"(gp[p]));
        }

        // horizontal add (even-sum + odd-sum) per c; register-pair halves, no movs needed
        float2 h0 = *reinterpret_cast<float2*>(&acc0);
        float2 h1 = *reinterpret_cast<float2*>(&acc1);
        float2 h2 = *reinterpret_cast<float2*>(&acc2);
        float2 h3 = *reinterpret_cast<float2*>(&acc3);
        float4 r = make_float4(h0.x + h0.y, h1.x + h1.y, h2.x + h2.y, h3.x + h3.y);

        *reinterpret_cast<float4*>(orow + (size_t)j * C_DIM) = r;   // STG.128
    }
}

extern "C" void kernel_launch(void* const* d_in, const int* in_sizes, int n_in,
                              void* d_out, int out_size)
{
    const float* f0 = (const float*)d_in[0];
    const float* f1 = (const float*)d_in[1];
    const float* f2 = (const float*)d_in[2];
    float* out = (float*)d_out;

    dim3 grid(B_DIM / BCHUNK, A_DIM);   // (8, 512) = 4096 blocks
    dim3 block(NTHREADS);
    parafac_kernel<<<grid, block>>>(f0, f1, f2, out);
}

// round 4
// speedup vs baseline: 1.0189x; 1.0189x over previous
#include <cuda_runtime.h>
#include <cstdint>

// PARAFAC / CP reconstruction: out[a,b,c] = sum_k f0[k,a] * f1[k,b] * f2[k,c]
// A = B = C = 512, RANK = 16, fp32. 536 MB output.
//
// Round-4: round-3 structure (k-paired f32x2, zero splat movs) + SOFTWARE PIPELINE:
//   - prefetch gsh[j+1] (4x LDS.128) into regs before j's FMA block -> LDS latency
//     (29 cyc) hidden behind ~40 issue slots; warps stay eligible.
//   - st.global.cs streaming stores (evict-first) for the pure-stream output.
//   - launch_bounds(128,4): room for the +16-reg prefetch buffer, no spills.

#define A_DIM 512
#define B_DIM 512
#define C_DIM 512
#define RANK  16
#define BCHUNK 64
#define NTHREADS 128   // 128 c-lanes x 4 c each = 512 c

typedef unsigned long long ull;

__device__ __forceinline__ ull pack2(float lo, float hi) {
    ull r;
    asm("mov.b64 %0, {%1,%2};" : "=l"(r) : "r"(__float_as_uint(lo)), "r"(__float_as_uint(hi)));
    return r;
}

__global__ __launch_bounds__(NTHREADS, 4)
void parafac_kernel(const float* __restrict__ f0,
                    const float* __restrict__ f1,
                    const float* __restrict__ f2,
                    float* __restrict__ out)
{
    // g k-major & contiguous: gsh[j][k] = f0[k][a]*f1[k][b0+j]
    __shared__ __align__(16) float gsh[BCHUNK][RANK];

    const int a  = blockIdx.y;
    const int b0 = blockIdx.x * BCHUNK;
    const int t  = threadIdx.x;
    const int c0 = t * 4;   // thread's fixed c-quad

    // ---- f2 transposed pack (once per block): f2p[p][c] = (f2[2p][c0+c], f2[2p+1][c0+c]) ----
    ull f2p[RANK / 2][4];
#pragma unroll
    for (int p = 0; p < RANK / 2; p++) {
        float4 e = *reinterpret_cast<const float4*>(f2 + (2 * p + 0) * C_DIM + c0);
        float4 o = *reinterpret_cast<const float4*>(f2 + (2 * p + 1) * C_DIM + c0);
        f2p[p][0] = pack2(e.x, o.x);
        f2p[p][1] = pack2(e.y, o.y);
        f2p[p][2] = pack2(e.z, o.z);
        f2p[p][3] = pack2(e.w, o.w);
    }

    // ---- precompute g: 64*16 = 1024 entries, 128 threads -> 8 each ----
#pragma unroll
    for (int i = 0; i < (BCHUNK * RANK) / NTHREADS; i++) {
        int idx = t + i * NTHREADS;
        int j = idx >> 4;     // b offset within chunk
        int k = idx & 15;     // rank index
        gsh[j][k] = f0[k * A_DIM + a] * f1[k * B_DIM + b0 + j];
    }
    __syncthreads();

    float* orow = out + (size_t)a * (B_DIM * C_DIM) + (size_t)b0 * C_DIM + c0;

    // ---- software-pipelined prefetch of g[j] ----
    ulonglong2 n0, n1, n2, n3;
    {
        const ulonglong2* g0 = reinterpret_cast<const ulonglong2*>(gsh[0]);
        n0 = g0[0]; n1 = g0[1]; n2 = g0[2]; n3 = g0[3];
    }

#pragma unroll 2
    for (int j = 0; j < BCHUNK; j++) {
        ull gp[RANK / 2] = { n0.x, n0.y, n1.x, n1.y, n2.x, n2.y, n3.x, n3.y };

        // prefetch next j (wrap on last iter -> redundant reload of gsh[0], harmless)
        const ulonglong2* gn =
            reinterpret_cast<const ulonglong2*>(gsh[(j + 1) & (BCHUNK - 1)]);
        n0 = gn[0]; n1 = gn[1]; n2 = gn[2]; n3 = gn[3];

        // 4 independent f32x2 accumulator chains (one per c); lanes = (even-k, odd-k) sums
        ull acc0 = 0ull, acc1 = 0ull, acc2 = 0ull, acc3 = 0ull;
#pragma unroll
        for (int p = 0; p < RANK / 2; p++) {
            asm("fma.rn.f32x2 %0, %1, %2, %0;" : "+l"(acc0) : "l"(f2p[p][0]), "l"(gp[p]));
            asm("fma.rn.f32x2 %0, %1, %2, %0;" : "+l"(acc1) : "l"(f2p[p][1]), "l"(gp[p]));
            asm("fma.rn.f32x2 %0, %1, %2, %0;" : "+l"(acc2) : "l"(f2p[p][2]), "l"(gp[p]));
            asm("fma.rn.f32x2 %0, %1, %2, %0;" : "+l"(acc3) : "l"(f2p[p][3]), "l"(gp[p]));
        }

        // horizontal add (even-sum + odd-sum) per c
        float2 h0 = *reinterpret_cast<float2*>(&acc0);
        float2 h1 = *reinterpret_cast<float2*>(&acc1);
        float2 h2 = *reinterpret_cast<float2*>(&acc2);
        float2 h3 = *reinterpret_cast<float2*>(&acc3);
        float r0 = h0.x + h0.y, r1 = h1.x + h1.y, r2 = h2.x + h2.y, r3 = h3.x + h3.y;

        // streaming STG.128 (evict-first)
        asm volatile("st.global.cs.v4.f32 [%0], {%1,%2,%3,%4};"
                     :: "l"(orow + (size_t)j * C_DIM),
                        "f"(r0), "f"(r1), "f"(r2), "f"(r3)
                     : "memory");
    }
}

extern "C" void kernel_launch(void* const* d_in, const int* in_sizes, int n_in,
                              void* d_out, int out_size)
{
    const float* f0 = (const float*)d_in[0];
    const float* f1 = (const float*)d_in[1];
    const float* f2 = (const float*)d_in[2];
    float* out = (float*)d_out;

    dim3 grid(B_DIM / BCHUNK, A_DIM);   // (8, 512) = 4096 blocks
    dim3 block(NTHREADS);
    parafac_kernel<<<grid, block>>>(f0, f1, f2, out);
}